// round 5
// baseline (speedup 1.0000x reference)
#include <cuda_runtime.h>

#define NN 64
#define CC 128
#define TT 2048
#define SS 9
#define CT 4               // output channels per WARP
#define JW (CT + SS - 1)   // 12 contributing input rows per warp
#define WPB 4              // warps per block
#define CPB (CT * WPB)     // 16 channels per block
#define TSPLIT 2           // T halves across blockIdx.z
#define EPS 1e-5f

__device__ float g_sum[CC];
__device__ float g_sqs[CC];

__global__ __launch_bounds__(128)
void conv_stats_kernel(const float* __restrict__ x,
                       const float* __restrict__ w,
                       float* __restrict__ out) {
    // grid: (CC/CPB=8, NN=64, TSPLIT=2), 128 threads.
    const int warp = threadIdx.x >> 5;
    const int lane = threadIdx.x & 31;
    const int c0   = blockIdx.x * CPB + warp * CT;  // this warp's first channel
    const int n    = blockIdx.y;
    const int t0   = blockIdx.z * (TT / TSPLIT);
    const int t1   = t0 + (TT / TSPLIT);

    // this warp's 36 weights -> registers
    float wr[CT][SS];
    #pragma unroll
    for (int dc = 0; dc < CT; dc++)
        #pragma unroll
        for (int s = 0; s < SS; s++)
            wr[dc][s] = __ldg(&w[(c0 + dc) * SS + s]);

    // contributing rows: cc = c0 - 4 + j. x used at output t is x[cc, t - sh(cc)],
    // sh(cc) = cc%9 - 4; zero outside [0,TT) in time or [0,CC) in channel.
    int cbase[JW], shv[JW];
    #pragma unroll
    for (int j = 0; j < JW; j++) {
        int cc = c0 - (SS / 2) + j;
        if (cc >= 0 && cc < CC) {
            cbase[j] = cc * TT;
            shv[j]   = (cc % SS) - (SS / 2);   // [-4, 4]
        } else {
            cbase[j] = 0;
            shv[j]   = 1 << 28;                // predicate always false
        }
    }

    const float* xb = x + (size_t)n * CC * TT;
    float* ob = out + ((size_t)n * CC + c0) * TT;

    float ssum[CT], ssq[CT];
    #pragma unroll
    for (int dc = 0; dc < CT; dc++) { ssum[dc] = 0.0f; ssq[dc] = 0.0f; }

    for (int t = t0 + lane; t < t1; t += 32) {
        float xv[JW];
        #pragma unroll
        for (int j = 0; j < JW; j++) {
            int ti = t - shv[j];
            xv[j] = ((unsigned)ti < (unsigned)TT) ? __ldg(xb + cbase[j] + ti) : 0.0f;
        }
        float acc[CT];
        #pragma unroll
        for (int dc = 0; dc < CT; dc++) acc[dc] = 0.0f;
        #pragma unroll
        for (int j = 0; j < JW; j++) {
            #pragma unroll
            for (int dc = 0; dc < CT; dc++) {
                int s = j - dc;
                if (s >= 0 && s < SS)
                    acc[dc] = fmaf(wr[dc][s], xv[j], acc[dc]);
            }
        }
        #pragma unroll
        for (int dc = 0; dc < CT; dc++) {
            ob[(size_t)dc * TT + t] = acc[dc];
            ssum[dc] += acc[dc];
            ssq[dc]   = fmaf(acc[dc], acc[dc], ssq[dc]);
        }
    }

    // warp-exclusive channels: shuffle-reduce, lane 0 atomics. No smem, no bar.
    #pragma unroll
    for (int dc = 0; dc < CT; dc++) {
        float a = ssum[dc], b = ssq[dc];
        #pragma unroll
        for (int off = 16; off > 0; off >>= 1) {
            a += __shfl_xor_sync(0xFFFFFFFFu, a, off);
            b += __shfl_xor_sync(0xFFFFFFFFu, b, off);
        }
        if (lane == 0) {
            atomicAdd(&g_sum[c0 + dc], a);
            atomicAdd(&g_sqs[c0 + dc], b);
        }
    }
}

__global__ __launch_bounds__(512)
void normalize_kernel(float* __restrict__ out,
                      const float* __restrict__ gamma,
                      const float* __restrict__ beta) {
    // one block per (n, c) row; 512 threads x float4 = 2048 elements
    const int b = blockIdx.x;
    const int c = b & (CC - 1);
    const float invM = 1.0f / (float)((size_t)NN * TT);
    float m  = g_sum[c] * invM;
    float v  = g_sqs[c] * invM - m * m;
    float is = rsqrtf(v + EPS);
    float sc = __ldg(&gamma[c]) * is;
    float bi = __ldg(&beta[c]) - m * sc;

    float4* p = reinterpret_cast<float4*>(out + (size_t)b * TT);
    float4 v4 = p[threadIdx.x];
    v4.x = fmaxf(fmaf(v4.x, sc, bi), 0.0f);
    v4.y = fmaxf(fmaf(v4.y, sc, bi), 0.0f);
    v4.z = fmaxf(fmaf(v4.z, sc, bi), 0.0f);
    v4.w = fmaxf(fmaf(v4.w, sc, bi), 0.0f);
    p[threadIdx.x] = v4;
}

__global__ void zero_stats_kernel() {
    // runs LAST: leaves stats zeroed for the next graph replay.
    // (__device__ globals are zero at module load, so replay 1 also sees zeros.)
    int i = threadIdx.x;
    if (i < CC) { g_sum[i] = 0.0f; g_sqs[i] = 0.0f; }
}

extern "C" void kernel_launch(void* const* d_in, const int* in_sizes, int n_in,
                              void* d_out, int out_size) {
    const float* x     = (const float*)d_in[0];   // (64,128,2048) f32
    const float* cw    = (const float*)d_in[1];   // (128,9)       f32
    const float* gamma = (const float*)d_in[2];   // (128,)        f32
    const float* beta  = (const float*)d_in[3];   // (128,)        f32
    float* out = (float*)d_out;                   // (64,128,2048) f32

    dim3 grid(CC / CPB, NN, TSPLIT);              // (8, 64, 2) = 1024 blocks
    conv_stats_kernel<<<grid, 128>>>(x, cw, out);
    normalize_kernel<<<NN * CC, 512>>>(out, gamma, beta);
    zero_stats_kernel<<<1, 128>>>();
}